// round 1
// baseline (speedup 1.0000x reference)
#include <cuda_runtime.h>
#include <cuda_bf16.h>
#include <math.h>

// ---------------------------------------------------------------------------
// Problem constants (fixed for this dataset entry)
// ---------------------------------------------------------------------------
#define BATCH   2
#define NQ      8192
#define EMBED   256
#define HEADS   8
#define DH      32
#define LEVELS  3
#define POINTS  4
#define MLPX    4
#define NV      6300          // 60*80 + 30*40 + 15*20
#define BQ      (BATCH * NQ)  // 16384 rows of queries
#define MV      (BATCH * NV)  // 12600 rows of value

// ---------------------------------------------------------------------------
// Scratch (device globals; allocation inside kernel_launch is forbidden)
// ---------------------------------------------------------------------------
__device__ float g_qn  [BQ * EMBED];        // layernorm1(query)
__device__ float g_qa  [BQ * EMBED];        // qn + query_pos
__device__ float g_offs[BQ * HEADS * LEVELS * POINTS * 2];   // 192 per row
__device__ float g_aw  [BQ * HEADS * LEVELS * POINTS];       // 96 per row (logits -> softmax in place)
__device__ float g_v   [MV * EMBED];        // value @ Wv + bv
__device__ float g_samp[BQ * EMBED];        // deformable attention output
__device__ float g_q   [BQ * EMBED];        // query + attn
__device__ float g_q2  [BQ * EMBED];        // layernorm2(q)
__device__ float g_hid [BQ * EMBED * MLPX]; // gelu(q2 @ Wf1 + bf1)

// ---------------------------------------------------------------------------
// LayerNorm: one warp per row of 256. Optionally also writes x_norm + pos.
// ---------------------------------------------------------------------------
__global__ void ln_kernel(const float* __restrict__ x,
                          const float* __restrict__ gamma,
                          const float* __restrict__ beta,
                          const float* __restrict__ pos,   // nullable
                          float* __restrict__ out_n,
                          float* __restrict__ out_a)       // nullable
{
    int warp = (blockIdx.x * blockDim.x + threadIdx.x) >> 5;
    int lane = threadIdx.x & 31;
    if (warp >= BQ) return;

    const float* xr = x + (size_t)warp * EMBED;
    float v[8];
    float s = 0.f;
#pragma unroll
    for (int i = 0; i < 8; i++) { v[i] = xr[i * 32 + lane]; s += v[i]; }
#pragma unroll
    for (int o = 16; o > 0; o >>= 1) s += __shfl_xor_sync(0xFFFFFFFFu, s, o);
    float mean = s * (1.f / EMBED);

    float s2 = 0.f;
#pragma unroll
    for (int i = 0; i < 8; i++) { float d = v[i] - mean; s2 += d * d; }
#pragma unroll
    for (int o = 16; o > 0; o >>= 1) s2 += __shfl_xor_sync(0xFFFFFFFFu, s2, o);
    float rstd = rsqrtf(s2 * (1.f / EMBED) + 1e-5f);

    size_t base = (size_t)warp * EMBED;
#pragma unroll
    for (int i = 0; i < 8; i++) {
        int c = i * 32 + lane;
        float nv = (v[i] - mean) * rstd * gamma[c] + beta[c];
        out_n[base + c] = nv;
        if (out_a) out_a[base + c] = nv + pos[base + c];
    }
}

// ---------------------------------------------------------------------------
// Generic tiled SGEMM: C[M,N] = A[M,K] @ W[K,N] + bias[N] (+add1 +add2) (gelu)
// 64x64 tile, BK=16, 256 threads, 4x4 per thread, float4 smem paths.
// Requires K % 16 == 0 (holds: K is 256 or 1024).
// ---------------------------------------------------------------------------
__global__ __launch_bounds__(256) void gemm64(
    const float* __restrict__ A, const float* __restrict__ W,
    const float* __restrict__ bias,
    const float* __restrict__ add1, const float* __restrict__ add2,
    float* __restrict__ C, int M, int N, int K, int gelu_flag)
{
    __shared__ float As[16][64];   // transposed: As[k][m]
    __shared__ float Bs[16][64];

    const int tid = threadIdx.x;
    const int tx = tid & 15;       // n-direction
    const int ty = tid >> 4;       // m-direction
    const int m0 = blockIdx.y * 64;
    const int n0 = blockIdx.x * 64;

    float acc[4][4];
#pragma unroll
    for (int i = 0; i < 4; i++)
#pragma unroll
        for (int j = 0; j < 4; j++) acc[i][j] = 0.f;

    const int ntiles = K >> 4;
    for (int kt = 0; kt < ntiles; kt++) {
        // --- load A tile: thread -> m = tid/4, kk = (tid&3)*4 (float4) ---
        {
            int ms = tid >> 2;
            int ks = (tid & 3) * 4;
            int m = m0 + ms;
            float4 av = make_float4(0.f, 0.f, 0.f, 0.f);
            if (m < M) av = *(const float4*)&A[(size_t)m * K + kt * 16 + ks];
            As[ks + 0][ms] = av.x;
            As[ks + 1][ms] = av.y;
            As[ks + 2][ms] = av.z;
            As[ks + 3][ms] = av.w;
        }
        // --- load B tile: thread -> k = tid/16, n = (tid&15)*4 ---
        {
            int k = kt * 16 + (tid >> 4);
            int nn = (tid & 15) * 4;
            int n = n0 + nn;
            float4 bv;
            if (n + 3 < N) {
                bv = *(const float4*)&W[(size_t)k * N + n];
            } else {
                bv.x = (n + 0 < N) ? W[(size_t)k * N + n + 0] : 0.f;
                bv.y = (n + 1 < N) ? W[(size_t)k * N + n + 1] : 0.f;
                bv.z = (n + 2 < N) ? W[(size_t)k * N + n + 2] : 0.f;
                bv.w = (n + 3 < N) ? W[(size_t)k * N + n + 3] : 0.f;
            }
            *(float4*)&Bs[tid >> 4][nn] = bv;
        }
        __syncthreads();

#pragma unroll
        for (int k = 0; k < 16; k++) {
            float4 a = *(const float4*)&As[k][ty * 4];
            float4 b = *(const float4*)&Bs[k][tx * 4];
            float av[4] = {a.x, a.y, a.z, a.w};
            float bv[4] = {b.x, b.y, b.z, b.w};
#pragma unroll
            for (int i = 0; i < 4; i++)
#pragma unroll
                for (int j = 0; j < 4; j++) acc[i][j] = fmaf(av[i], bv[j], acc[i][j]);
        }
        __syncthreads();
    }

    // --- epilogue ---
#pragma unroll
    for (int i = 0; i < 4; i++) {
        int m = m0 + ty * 4 + i;
        if (m >= M) continue;
#pragma unroll
        for (int j = 0; j < 4; j++) {
            int n = n0 + tx * 4 + j;
            if (n >= N) continue;
            size_t idx = (size_t)m * N + n;
            float val = acc[i][j] + bias[n];
            if (add1) val += add1[idx];
            if (add2) val += add2[idx];
            if (gelu_flag) val = 0.5f * val * (1.f + erff(val * 0.70710678118654752f));
            C[idx] = val;
        }
    }
}

// ---------------------------------------------------------------------------
// Softmax over the 12 (levels*points) logits per (b,q,h), in place.
// ---------------------------------------------------------------------------
__global__ void softmax12(float* __restrict__ logits)
{
    int t = blockIdx.x * blockDim.x + threadIdx.x;
    if (t >= BQ * HEADS) return;
    int bq = t >> 3;
    int h = t & 7;
    float* row = logits + (size_t)bq * (HEADS * LEVELS * POINTS) + h * (LEVELS * POINTS);
    float v[12];
    float mx = -1e30f;
#pragma unroll
    for (int i = 0; i < 12; i++) { v[i] = row[i]; mx = fmaxf(mx, v[i]); }
    float s = 0.f;
#pragma unroll
    for (int i = 0; i < 12; i++) { v[i] = __expf(v[i] - mx); s += v[i]; }
    float inv = 1.f / s;
#pragma unroll
    for (int i = 0; i < 12; i++) row[i] = v[i] * inv;
}

// ---------------------------------------------------------------------------
// Deformable sampling: one warp per (b,q,h); lane = channel within head.
// ---------------------------------------------------------------------------
__global__ void sample_kernel(const float* __restrict__ v,
                              const float* __restrict__ offs,
                              const float* __restrict__ aw,
                              const float* __restrict__ ref,
                              float* __restrict__ out)
{
    const int LH[3] = {60, 30, 15};
    const int LW[3] = {80, 40, 20};
    const int LS[3] = {0, 4800, 6000};

    int warp = (blockIdx.x * blockDim.x + threadIdx.x) >> 5;
    int lane = threadIdx.x & 31;
    if (warp >= BQ * HEADS) return;

    int h  = warp & 7;
    int bq = warp >> 3;
    int b  = bq / NQ;

    float acc = 0.f;

    const float* offr = offs + (size_t)bq * 192 + h * 24;
    const float* awr  = aw   + (size_t)bq * 96  + h * 12;
    const float* refr = ref  + (size_t)bq * (LEVELS * 2);

#pragma unroll
    for (int l = 0; l < LEVELS; l++) {
        const int Hl = LH[l], Wl = LW[l];
        const float rx = refr[l * 2 + 0] * (float)Wl - 0.5f;
        const float ry = refr[l * 2 + 1] * (float)Hl - 0.5f;
        const float* vb = v + (((size_t)b * NV + LS[l]) * EMBED) + h * DH + lane;

#pragma unroll
        for (int p = 0; p < POINTS; p++) {
            float gx = rx + offr[l * 8 + p * 2 + 0];
            float gy = ry + offr[l * 8 + p * 2 + 1];
            float x0f = floorf(gx), y0f = floorf(gy);
            float wx = gx - x0f, wy = gy - y0f;
            int x0 = (int)x0f, y0 = (int)y0f;

            float w00 = (1.f - wx) * (1.f - wy);
            float w10 = wx * (1.f - wy);
            float w01 = (1.f - wx) * wy;
            float w11 = wx * wy;

            bool xv0 = (x0 >= 0) & (x0 < Wl);
            bool xv1 = (x0 + 1 >= 0) & (x0 + 1 < Wl);
            bool yv0 = (y0 >= 0) & (y0 < Hl);
            bool yv1 = (y0 + 1 >= 0) & (y0 + 1 < Hl);

            float s = 0.f;
            if (xv0 & yv0) s += w00 * vb[((size_t)(y0 * Wl + x0)) * EMBED];
            if (xv1 & yv0) s += w10 * vb[((size_t)(y0 * Wl + x0 + 1)) * EMBED];
            if (xv0 & yv1) s += w01 * vb[((size_t)((y0 + 1) * Wl + x0)) * EMBED];
            if (xv1 & yv1) s += w11 * vb[((size_t)((y0 + 1) * Wl + x0 + 1)) * EMBED];

            acc = fmaf(awr[l * 4 + p], s, acc);
        }
    }

    out[(size_t)bq * EMBED + h * DH + lane] = acc;
}

// ---------------------------------------------------------------------------
// Launch
// ---------------------------------------------------------------------------
extern "C" void kernel_launch(void* const* d_in, const int* in_sizes, int n_in,
                              void* d_out, int out_size)
{
    (void)in_sizes; (void)n_in; (void)out_size;

    const float* query = (const float*)d_in[0];
    const float* value = (const float*)d_in[1];
    const float* qpos  = (const float*)d_in[2];
    const float* refp  = (const float*)d_in[3];
    // d_in[4] spatial_shapes, d_in[5] level_start_index: hardcoded constants
    const float* g1  = (const float*)d_in[6];
    const float* b1  = (const float*)d_in[7];
    const float* Wo  = (const float*)d_in[8];
    const float* bo  = (const float*)d_in[9];
    const float* Wa  = (const float*)d_in[10];
    const float* ba  = (const float*)d_in[11];
    const float* Wv  = (const float*)d_in[12];
    const float* bv  = (const float*)d_in[13];
    const float* Wp  = (const float*)d_in[14];
    const float* bp  = (const float*)d_in[15];
    const float* g2  = (const float*)d_in[16];
    const float* b2  = (const float*)d_in[17];
    const float* Wf1 = (const float*)d_in[18];
    const float* bf1 = (const float*)d_in[19];
    const float* Wf2 = (const float*)d_in[20];
    const float* bf2 = (const float*)d_in[21];
    float* out = (float*)d_out;

    float *qn, *qa, *offs, *aw, *v, *samp, *q, *q2, *hid;
    cudaGetSymbolAddress((void**)&qn,   g_qn);
    cudaGetSymbolAddress((void**)&qa,   g_qa);
    cudaGetSymbolAddress((void**)&offs, g_offs);
    cudaGetSymbolAddress((void**)&aw,   g_aw);
    cudaGetSymbolAddress((void**)&v,    g_v);
    cudaGetSymbolAddress((void**)&samp, g_samp);
    cudaGetSymbolAddress((void**)&q,    g_q);
    cudaGetSymbolAddress((void**)&q2,   g_q2);
    cudaGetSymbolAddress((void**)&hid,  g_hid);

    const int LN_BLOCKS = (BQ * 32) / 256;            // 2048

    // 1. qn = LN1(query); qa = qn + query_pos
    ln_kernel<<<LN_BLOCKS, 256>>>(query, g1, b1, qpos, qn, qa);

    // 2. offsets and attention logits
    gemm64<<<dim3(3, BQ / 64), 256>>>(qa, Wo, bo, nullptr, nullptr, offs, BQ, 192, EMBED, 0);
    gemm64<<<dim3(2, BQ / 64), 256>>>(qa, Wa, ba, nullptr, nullptr, aw,   BQ,  96, EMBED, 0);

    // 3. softmax over 12
    softmax12<<<(BQ * HEADS + 255) / 256, 256>>>(aw);

    // 4. value projection
    gemm64<<<dim3(4, (MV + 63) / 64), 256>>>(value, Wv, bv, nullptr, nullptr, v, MV, EMBED, EMBED, 0);

    // 5. deformable sampling
    sample_kernel<<<(BQ * HEADS * 32) / 256, 256>>>(v, offs, aw, refp, samp);

    // 6. q = samp @ Wp + bp + qn + query
    gemm64<<<dim3(4, BQ / 64), 256>>>(samp, Wp, bp, qn, query, q, BQ, EMBED, EMBED, 0);

    // 7. q2 = LN2(q)
    ln_kernel<<<LN_BLOCKS, 256>>>(q, g2, b2, nullptr, q2, nullptr);

    // 8. hid = gelu(q2 @ Wf1 + bf1)
    gemm64<<<dim3(16, BQ / 64), 256>>>(q2, Wf1, bf1, nullptr, nullptr, hid, BQ, EMBED * MLPX, EMBED, 1);

    // 9. out = q + hid @ Wf2 + bf2
    gemm64<<<dim3(4, BQ / 64), 256>>>(hid, Wf2, bf2, q, nullptr, out, BQ, EMBED, EMBED * MLPX, 0);
}

// round 4
// speedup vs baseline: 4.2480x; 4.2480x over previous
#include <cuda_runtime.h>
#include <cuda_bf16.h>
#include <math.h>
#include <stdint.h>

// ---------------------------------------------------------------------------
// Problem constants
// ---------------------------------------------------------------------------
#define BATCH   2
#define NQ      8192
#define EMBED   256
#define HEADS   8
#define DH      32
#define LEVELS  3
#define POINTS  4
#define NV      6300
#define BQ      (BATCH * NQ)   // 16384
#define MV      (BATCH * NV)   // 12600

// ---------------------------------------------------------------------------
// Scratch (device globals)
// ---------------------------------------------------------------------------
__device__ float g_qn  [BQ * EMBED];
__device__ float g_qa  [BQ * EMBED];     // tf32-rounded
__device__ float g_offs[BQ * 192];
__device__ float g_aw  [BQ * 96];
__device__ float g_vr  [MV * EMBED];     // tf32-rounded copy of value
__device__ float g_v   [MV * EMBED];     // value @ Wv + bv
__device__ float g_samp[BQ * EMBED];     // tf32-rounded
__device__ float g_q   [BQ * EMBED];
__device__ float g_q2  [BQ * EMBED];     // tf32-rounded
__device__ float g_hid [BQ * 1024];      // tf32-rounded
__device__ float g_WT  [729088];         // transposed weights [N][K], tf32-rounded

#define WT_O   0        // 192 x 256
#define WT_A   49152    //  96 x 256
#define WT_V   73728    // 256 x 256
#define WT_P   139264   // 256 x 256
#define WT_F1  204800   // 1024 x 256
#define WT_F2  466944   // 256 x 1024

// ---------------------------------------------------------------------------
// Helpers
// ---------------------------------------------------------------------------
__device__ __forceinline__ float to_tf32(float x) {
    float r;
    asm("cvt.rna.tf32.f32 %0, %1;" : "=f"(r) : "f"(x));
    return r;
}
__device__ __forceinline__ uint32_t smem_u32(const void* p) {
    uint32_t a;
    asm("{ .reg .u64 t; cvta.to.shared.u64 t, %1; cvt.u32.u64 %0, t; }"
        : "=r"(a) : "l"(p));
    return a;
}
#define CP_ASYNC16(dst, src, sz) \
    asm volatile("cp.async.cg.shared.global [%0], [%1], 16, %2;" \
                 :: "r"(dst), "l"(src), "r"(sz) : "memory")
#define CP_COMMIT() asm volatile("cp.async.commit_group;" ::: "memory")
#define CP_WAIT1()  asm volatile("cp.async.wait_group 1;" ::: "memory")
#define CP_WAIT0()  asm volatile("cp.async.wait_group 0;" ::: "memory")

__device__ __forceinline__ void mma_tf32(float* c,
                                         float a0, float a1, float a2, float a3,
                                         float b0, float b1) {
    uint32_t A0 = __float_as_uint(a0), A1 = __float_as_uint(a1);
    uint32_t A2 = __float_as_uint(a2), A3 = __float_as_uint(a3);
    uint32_t B0 = __float_as_uint(b0), B1 = __float_as_uint(b1);
    asm volatile(
        "mma.sync.aligned.m16n8k8.row.col.f32.tf32.tf32.f32 "
        "{%0,%1,%2,%3}, {%4,%5,%6,%7}, {%8,%9}, {%0,%1,%2,%3};"
        : "+f"(c[0]), "+f"(c[1]), "+f"(c[2]), "+f"(c[3])
        : "r"(A0), "r"(A1), "r"(A2), "r"(A3), "r"(B0), "r"(B1));
}

// ---------------------------------------------------------------------------
// Weight transpose + tf32 round: WT[n][k] = tf32(W[k][n])
// ---------------------------------------------------------------------------
__global__ void transpose_all(const float* __restrict__ W0, const float* __restrict__ W1,
                              const float* __restrict__ W2, const float* __restrict__ W3,
                              const float* __restrict__ W4, const float* __restrict__ W5,
                              float* __restrict__ WT)
{
    __shared__ float t[32][33];
    const int seg = blockIdx.z;
    const int Ks[6]  = {256, 256, 256, 256, 256, 1024};
    const int Ns[6]  = {192,  96, 256, 256, 1024, 256};
    const int Off[6] = {WT_O, WT_A, WT_V, WT_P, WT_F1, WT_F2};
    const float* src = seg == 0 ? W0 : seg == 1 ? W1 : seg == 2 ? W2 :
                       seg == 3 ? W3 : seg == 4 ? W4 : W5;
    const int K = Ks[seg], N = Ns[seg];
    float* dst = WT + Off[seg];

    int bx = blockIdx.x * 32;   // n block
    int by = blockIdx.y * 32;   // k block
    if (bx >= N || by >= K) return;

    int x = bx + threadIdx.x;
#pragma unroll
    for (int j = 0; j < 32; j += 8) {
        int y = by + threadIdx.y + j;
        if (x < N && y < K) t[threadIdx.y + j][threadIdx.x] = src[(size_t)y * N + x];
    }
    __syncthreads();
    x = by + threadIdx.x;
#pragma unroll
    for (int j = 0; j < 32; j += 8) {
        int y = bx + threadIdx.y + j;
        if (x < K && y < N) dst[(size_t)y * K + x] = to_tf32(t[threadIdx.x][threadIdx.y + j]);
    }
}

// Round value input to tf32 once
__global__ void round_kernel(const float* __restrict__ src, float* __restrict__ dst, int n)
{
    int i = blockIdx.x * blockDim.x + threadIdx.x;
    if (i < n) dst[i] = to_tf32(src[i]);
}

// ---------------------------------------------------------------------------
// tf32 HMMA GEMM: C[M,N] = A[M,K] @ W[K,N] (+bias +add1 +add2, opt gelu)
// WT: pre-transposed [N][K]. CTA 128x128, BK=32, 8 warps of 64x32.
// A,WT must already be tf32-rounded (HW truncation is then exact).
// ---------------------------------------------------------------------------
#define PAD       36                  // floats per 32-float row (bank-conflict-free)
#define A_STAGE   (128 * PAD)         // 4608 floats
#define SM_FLOATS (4 * A_STAGE)       // A0,A1,B0,B1 -> 18432 floats = 73728 B
#define SM_BYTES  (SM_FLOATS * 4)

__global__ __launch_bounds__(256) void gemm_mma(
    const float* __restrict__ A, const float* __restrict__ WT,
    const float* __restrict__ bias, const float* __restrict__ add1,
    const float* __restrict__ add2, float* __restrict__ C,
    int M, int N, int K, int gelu_flag)
{
    extern __shared__ float sm[];
    const uint32_t sbase = smem_u32(sm);
    const int tid  = threadIdx.x;
    const int wid  = tid >> 5;
    const int lane = tid & 31;
    const int wm   = wid >> 2;        // 0..1 (64 rows each)
    const int wn   = wid & 3;         // 0..3 (32 cols each)
    const int g    = lane >> 2;       // 0..7
    const int c    = lane & 3;        // 0..3
    const int m0   = blockIdx.y * 128;
    const int n0   = blockIdx.x * 128;

    float acc[4][4][4];
#pragma unroll
    for (int i = 0; i < 4; i++)
#pragma unroll
        for (int j = 0; j < 4; j++)
#pragma unroll
            for (int r = 0; r < 4; r++) acc[i][j][r] = 0.f;

    const int nk = K >> 5;

    // ---- tile loader via cp.async ----
    auto load_tile = [&](int s, int kt) {
        const int k0 = kt * 32;
#pragma unroll
        for (int t = 0; t < 4; t++) {
            int idx = tid + t * 256;
            int row = idx >> 3, j = idx & 7;
            int gm = m0 + row;
            int sz = (gm < M) ? 16 : 0;
            const float* src = A + (size_t)(sz ? gm : 0) * K + k0 + j * 4;
            uint32_t dst = sbase + (uint32_t)((s * A_STAGE + row * PAD + j * 4) * 4);
            CP_ASYNC16(dst, src, sz);
        }
#pragma unroll
        for (int t = 0; t < 4; t++) {
            int idx = tid + t * 256;
            int row = idx >> 3, j = idx & 7;
            int gn = n0 + row;
            int sz = (gn < N) ? 16 : 0;
            const float* src = WT + (size_t)(sz ? gn : 0) * K + k0 + j * 4;
            uint32_t dst = sbase + (uint32_t)((2 * A_STAGE + s * A_STAGE + row * PAD + j * 4) * 4);
            CP_ASYNC16(dst, src, sz);
        }
    };

    load_tile(0, 0);
    CP_COMMIT();

    for (int kt = 0; kt < nk; kt++) {
        const int s = kt & 1;
        if (kt + 1 < nk) {
            load_tile(s ^ 1, kt + 1);
            CP_COMMIT();
            CP_WAIT1();
        } else {
            CP_WAIT0();
        }
        __syncthreads();

        const float* Apt = sm + s * A_STAGE;
        const float* Bpt = sm + 2 * A_STAGE + s * A_STAGE;

#pragma unroll
        for (int k8 = 0; k8 < 4; k8++) {
            const int kk = k8 * 8;
            float a[4][4], b[4][2];
#pragma unroll
            for (int mi = 0; mi < 4; mi++) {
                int r = wm * 64 + mi * 16 + g;
                a[mi][0] = Apt[r * PAD + kk + c];
                a[mi][1] = Apt[(r + 8) * PAD + kk + c];
                a[mi][2] = Apt[r * PAD + kk + c + 4];
                a[mi][3] = Apt[(r + 8) * PAD + kk + c + 4];
            }
#pragma unroll
            for (int ni = 0; ni < 4; ni++) {
                int n = wn * 32 + ni * 8 + g;
                b[ni][0] = Bpt[n * PAD + kk + c];
                b[ni][1] = Bpt[n * PAD + kk + c + 4];
            }
#pragma unroll
            for (int mi = 0; mi < 4; mi++)
#pragma unroll
                for (int ni = 0; ni < 4; ni++)
                    mma_tf32(acc[mi][ni], a[mi][0], a[mi][1], a[mi][2], a[mi][3],
                             b[ni][0], b[ni][1]);
        }
        __syncthreads();
    }

    // ---- epilogue ----
#pragma unroll
    for (int mi = 0; mi < 4; mi++) {
#pragma unroll
        for (int ni = 0; ni < 4; ni++) {
            int row = m0 + wm * 64 + mi * 16 + g;
            int col = n0 + wn * 32 + ni * 8 + c * 2;
            if (col >= N) continue;
            float2 bs = *(const float2*)&bias[col];
#pragma unroll
            for (int half = 0; half < 2; half++) {
                int r = row + half * 8;
                if (r >= M) continue;
                size_t idx = (size_t)r * N + col;
                float vx = acc[mi][ni][half * 2 + 0] + bs.x;
                float vy = acc[mi][ni][half * 2 + 1] + bs.y;
                if (add1) {
                    float2 a1 = *(const float2*)&add1[idx];
                    vx += a1.x; vy += a1.y;
                }
                if (add2) {
                    float2 a2 = *(const float2*)&add2[idx];
                    vx += a2.x; vy += a2.y;
                }
                if (gelu_flag) {
                    vx = 0.5f * vx * (1.f + erff(vx * 0.70710678118654752f));
                    vy = 0.5f * vy * (1.f + erff(vy * 0.70710678118654752f));
                    vx = to_tf32(vx);   // hid is consumed as GEMM A operand
                    vy = to_tf32(vy);
                }
                float2 o; o.x = vx; o.y = vy;
                *(float2*)&C[idx] = o;
            }
        }
    }
}

// ---------------------------------------------------------------------------
// LayerNorm: one warp per row of 256.
// round_n: round out_n to tf32 (when out_n feeds a GEMM A operand).
// out_a (if present) is always tf32-rounded (qa).
// ---------------------------------------------------------------------------
__global__ void ln_kernel(const float* __restrict__ x,
                          const float* __restrict__ gamma,
                          const float* __restrict__ beta,
                          const float* __restrict__ pos,
                          float* __restrict__ out_n,
                          float* __restrict__ out_a,
                          int round_n)
{
    int warp = (blockIdx.x * blockDim.x + threadIdx.x) >> 5;
    int lane = threadIdx.x & 31;
    if (warp >= BQ) return;

    const float* xr = x + (size_t)warp * EMBED;
    float v[8];
    float s = 0.f;
#pragma unroll
    for (int i = 0; i < 8; i++) { v[i] = xr[i * 32 + lane]; s += v[i]; }
#pragma unroll
    for (int o = 16; o > 0; o >>= 1) s += __shfl_xor_sync(0xFFFFFFFFu, s, o);
    float mean = s * (1.f / EMBED);

    float s2 = 0.f;
#pragma unroll
    for (int i = 0; i < 8; i++) { float d = v[i] - mean; s2 += d * d; }
#pragma unroll
    for (int o = 16; o > 0; o >>= 1) s2 += __shfl_xor_sync(0xFFFFFFFFu, s2, o);
    float rstd = rsqrtf(s2 * (1.f / EMBED) + 1e-5f);

    size_t base = (size_t)warp * EMBED;
#pragma unroll
    for (int i = 0; i < 8; i++) {
        int cidx = i * 32 + lane;
        float nv = (v[i] - mean) * rstd * gamma[cidx] + beta[cidx];
        out_n[base + cidx] = round_n ? to_tf32(nv) : nv;
        if (out_a) out_a[base + cidx] = to_tf32(nv + pos[base + cidx]);
    }
}

// ---------------------------------------------------------------------------
// Softmax over the 12 logits per (b,q,h), in place.
// ---------------------------------------------------------------------------
__global__ void softmax12(float* __restrict__ logits)
{
    int t = blockIdx.x * blockDim.x + threadIdx.x;
    if (t >= BQ * HEADS) return;
    int bq = t >> 3;
    int h = t & 7;
    float* row = logits + (size_t)bq * 96 + h * 12;
    float v[12];
    float mx = -1e30f;
#pragma unroll
    for (int i = 0; i < 12; i++) { v[i] = row[i]; mx = fmaxf(mx, v[i]); }
    float s = 0.f;
#pragma unroll
    for (int i = 0; i < 12; i++) { v[i] = __expf(v[i] - mx); s += v[i]; }
    float inv = 1.f / s;
#pragma unroll
    for (int i = 0; i < 12; i++) row[i] = v[i] * inv;
}

// ---------------------------------------------------------------------------
// Deformable sampling: one warp per (b,q,h); lane = channel within head.
// Output rounded to tf32 (feeds GEMM P as A).
// ---------------------------------------------------------------------------
__global__ void sample_kernel(const float* __restrict__ v,
                              const float* __restrict__ offs,
                              const float* __restrict__ aw,
                              const float* __restrict__ ref,
                              float* __restrict__ out)
{
    const int LH[3] = {60, 30, 15};
    const int LW[3] = {80, 40, 20};
    const int LS[3] = {0, 4800, 6000};

    int warp = (blockIdx.x * blockDim.x + threadIdx.x) >> 5;
    int lane = threadIdx.x & 31;
    if (warp >= BQ * HEADS) return;

    int h  = warp & 7;
    int bq = warp >> 3;
    int b  = bq / NQ;

    float acc = 0.f;
    const float* offr = offs + (size_t)bq * 192 + h * 24;
    const float* awr  = aw   + (size_t)bq * 96  + h * 12;
    const float* refr = ref  + (size_t)bq * (LEVELS * 2);

#pragma unroll
    for (int l = 0; l < LEVELS; l++) {
        const int Hl = LH[l], Wl = LW[l];
        const float rx = refr[l * 2 + 0] * (float)Wl - 0.5f;
        const float ry = refr[l * 2 + 1] * (float)Hl - 0.5f;
        const float* vb = v + (((size_t)b * NV + LS[l]) * EMBED) + h * DH + lane;

#pragma unroll
        for (int p = 0; p < POINTS; p++) {
            float gx = rx + offr[l * 8 + p * 2 + 0];
            float gy = ry + offr[l * 8 + p * 2 + 1];
            float x0f = floorf(gx), y0f = floorf(gy);
            float wx = gx - x0f, wy = gy - y0f;
            int x0 = (int)x0f, y0 = (int)y0f;

            float w00 = (1.f - wx) * (1.f - wy);
            float w10 = wx * (1.f - wy);
            float w01 = (1.f - wx) * wy;
            float w11 = wx * wy;

            bool xv0 = (x0 >= 0) & (x0 < Wl);
            bool xv1 = (x0 + 1 >= 0) & (x0 + 1 < Wl);
            bool yv0 = (y0 >= 0) & (y0 < Hl);
            bool yv1 = (y0 + 1 >= 0) & (y0 + 1 < Hl);

            float sv = 0.f;
            if (xv0 & yv0) sv += w00 * vb[((size_t)(y0 * Wl + x0)) * EMBED];
            if (xv1 & yv0) sv += w10 * vb[((size_t)(y0 * Wl + x0 + 1)) * EMBED];
            if (xv0 & yv1) sv += w01 * vb[((size_t)((y0 + 1) * Wl + x0)) * EMBED];
            if (xv1 & yv1) sv += w11 * vb[((size_t)((y0 + 1) * Wl + x0 + 1)) * EMBED];

            acc = fmaf(awr[l * 4 + p], sv, acc);
        }
    }

    out[(size_t)bq * EMBED + h * DH + lane] = to_tf32(acc);
}

// ---------------------------------------------------------------------------
// Launch
// ---------------------------------------------------------------------------
extern "C" void kernel_launch(void* const* d_in, const int* in_sizes, int n_in,
                              void* d_out, int out_size)
{
    (void)in_sizes; (void)n_in; (void)out_size;

    const float* query = (const float*)d_in[0];
    const float* value = (const float*)d_in[1];
    const float* qpos  = (const float*)d_in[2];
    const float* refp  = (const float*)d_in[3];
    const float* g1  = (const float*)d_in[6];
    const float* b1  = (const float*)d_in[7];
    const float* Wo  = (const float*)d_in[8];
    const float* bo  = (const float*)d_in[9];
    const float* Wa  = (const float*)d_in[10];
    const float* ba  = (const float*)d_in[11];
    const float* Wv  = (const float*)d_in[12];
    const float* bv  = (const float*)d_in[13];
    const float* Wp  = (const float*)d_in[14];
    const float* bp  = (const float*)d_in[15];
    const float* g2  = (const float*)d_in[16];
    const float* b2  = (const float*)d_in[17];
    const float* Wf1 = (const float*)d_in[18];
    const float* bf1 = (const float*)d_in[19];
    const float* Wf2 = (const float*)d_in[20];
    const float* bf2 = (const float*)d_in[21];
    float* out = (float*)d_out;

    float *qn, *qa, *offs, *aw, *vr, *v, *samp, *q, *q2, *hid, *wt;
    cudaGetSymbolAddress((void**)&qn,   g_qn);
    cudaGetSymbolAddress((void**)&qa,   g_qa);
    cudaGetSymbolAddress((void**)&offs, g_offs);
    cudaGetSymbolAddress((void**)&aw,   g_aw);
    cudaGetSymbolAddress((void**)&vr,   g_vr);
    cudaGetSymbolAddress((void**)&v,    g_v);
    cudaGetSymbolAddress((void**)&samp, g_samp);
    cudaGetSymbolAddress((void**)&q,    g_q);
    cudaGetSymbolAddress((void**)&q2,   g_q2);
    cudaGetSymbolAddress((void**)&hid,  g_hid);
    cudaGetSymbolAddress((void**)&wt,   g_WT);

    cudaFuncSetAttribute(gemm_mma, cudaFuncAttributeMaxDynamicSharedMemorySize, SM_BYTES);

    // 0. transpose + tf32-round weights; round value
    transpose_all<<<dim3(32, 32, 6), dim3(32, 8)>>>(Wo, Wa, Wv, Wp, Wf1, Wf2, wt);
    round_kernel<<<(MV * EMBED + 255) / 256, 256>>>(value, vr, MV * EMBED);

    // 1. qn = LN1(query) (fp32); qa = tf32(qn + query_pos)
    ln_kernel<<<2048, 256>>>(query, g1, b1, qpos, qn, qa, 0);

    // 2. offsets and attention logits
    gemm_mma<<<dim3(2, 128), 256, SM_BYTES>>>(qa, wt + WT_O, bo, nullptr, nullptr, offs,
                                              BQ, 192, 256, 0);
    gemm_mma<<<dim3(1, 128), 256, SM_BYTES>>>(qa, wt + WT_A, ba, nullptr, nullptr, aw,
                                              BQ, 96, 256, 0);

    // 3. softmax over 12
    softmax12<<<(BQ * HEADS + 255) / 256, 256>>>(aw);

    // 4. value projection
    gemm_mma<<<dim3(2, 99), 256, SM_BYTES>>>(vr, wt + WT_V, bv, nullptr, nullptr, v,
                                             MV, 256, 256, 0);

    // 5. deformable sampling (out tf32-rounded)
    sample_kernel<<<(BQ * HEADS * 32) / 256, 256>>>(v, offs, aw, refp, samp);

    // 6. q = samp @ Wp + bp + qn + query
    gemm_mma<<<dim3(2, 128), 256, SM_BYTES>>>(samp, wt + WT_P, bp, qn, query, q,
                                              BQ, 256, 256, 0);

    // 7. q2 = tf32(LN2(q))
    ln_kernel<<<2048, 256>>>(q, g2, b2, nullptr, q2, nullptr, 1);

    // 8. hid = tf32(gelu(q2 @ Wf1 + bf1))
    gemm_mma<<<dim3(8, 128), 256, SM_BYTES>>>(q2, wt + WT_F1, bf1, nullptr, nullptr, hid,
                                              BQ, 1024, 256, 1);

    // 9. out = q + hid @ Wf2 + bf2
    gemm_mma<<<dim3(2, 128), 256, SM_BYTES>>>(hid, wt + WT_F2, bf2, q, nullptr, out,
                                              BQ, 256, 1024, 0);
}

// round 5
// speedup vs baseline: 5.1212x; 1.2056x over previous
#include <cuda_runtime.h>
#include <cuda_bf16.h>
#include <math.h>
#include <stdint.h>

// ---------------------------------------------------------------------------
// Problem constants
// ---------------------------------------------------------------------------
#define BATCH   2
#define NQ      8192
#define EMBED   256
#define HEADS   8
#define DH      32
#define LEVELS  3
#define POINTS  4
#define NV      6300
#define BQ      (BATCH * NQ)   // 16384
#define MV      (BATCH * NV)   // 12600

// ---------------------------------------------------------------------------
// Scratch (device globals)
// ---------------------------------------------------------------------------
__device__ float          g_qn  [BQ * EMBED];   // LN1(query), fp32
__device__ __nv_bfloat16  g_qa  [BQ * EMBED];   // bf16(qn + query_pos)
__device__ float          g_offs[BQ * 192];
__device__ float          g_aw  [BQ * 96];      // logits (softmax fused into sampling)
__device__ __nv_bfloat16  g_vr  [MV * EMBED];   // bf16(value)
__device__ float          g_v   [MV * EMBED];   // value @ Wv + bv, fp32
__device__ __nv_bfloat16  g_samp[BQ * EMBED];   // bf16 sampled output
__device__ float          g_q   [BQ * EMBED];
__device__ __nv_bfloat16  g_q2  [BQ * EMBED];   // bf16(LN2(q))
__device__ __nv_bfloat16  g_hid [BQ * 1024];    // bf16(gelu(...))
__device__ __nv_bfloat16  g_WT  [729088];       // transposed weights [N][K], bf16

#define WT_O   0        // 192 x 256
#define WT_A   49152    //  96 x 256
#define WT_V   73728    // 256 x 256
#define WT_P   139264   // 256 x 256
#define WT_F1  204800   // 1024 x 256
#define WT_F2  466944   // 256 x 1024

// ---------------------------------------------------------------------------
// Helpers
// ---------------------------------------------------------------------------
__device__ __forceinline__ uint32_t smem_u32(const void* p) {
    uint32_t a;
    asm("{ .reg .u64 t; cvta.to.shared.u64 t, %1; cvt.u32.u64 %0, t; }"
        : "=r"(a) : "l"(p));
    return a;
}
#define CP_ASYNC16(dst, src, sz) \
    asm volatile("cp.async.cg.shared.global [%0], [%1], 16, %2;" \
                 :: "r"(dst), "l"(src), "r"(sz) : "memory")
#define CP_COMMIT() asm volatile("cp.async.commit_group;" ::: "memory")
#define CP_WAIT1()  asm volatile("cp.async.wait_group 1;" ::: "memory")
#define CP_WAIT0()  asm volatile("cp.async.wait_group 0;" ::: "memory")

#define LDSM_X4(r0, r1, r2, r3, addr) \
    asm volatile("ldmatrix.sync.aligned.m8n8.x4.shared.b16 {%0,%1,%2,%3}, [%4];" \
                 : "=r"(r0), "=r"(r1), "=r"(r2), "=r"(r3) : "r"(addr))

__device__ __forceinline__ void mma_bf16(float* c, const uint32_t* a, const uint32_t* b) {
    asm volatile(
        "mma.sync.aligned.m16n8k16.row.col.f32.bf16.bf16.f32 "
        "{%0,%1,%2,%3}, {%4,%5,%6,%7}, {%8,%9}, {%0,%1,%2,%3};"
        : "+f"(c[0]), "+f"(c[1]), "+f"(c[2]), "+f"(c[3])
        : "r"(a[0]), "r"(a[1]), "r"(a[2]), "r"(a[3]), "r"(b[0]), "r"(b[1]));
}

// ---------------------------------------------------------------------------
// Weight transpose + bf16 round: WT[n][k] = bf16(W[k][n])
// ---------------------------------------------------------------------------
__global__ void transpose_all(const float* __restrict__ W0, const float* __restrict__ W1,
                              const float* __restrict__ W2, const float* __restrict__ W3,
                              const float* __restrict__ W4, const float* __restrict__ W5,
                              __nv_bfloat16* __restrict__ WT)
{
    __shared__ float t[32][33];
    const int seg = blockIdx.z;
    const int Ks[6]  = {256, 256, 256, 256, 256, 1024};
    const int Ns[6]  = {192,  96, 256, 256, 1024, 256};
    const int Off[6] = {WT_O, WT_A, WT_V, WT_P, WT_F1, WT_F2};
    const float* src = seg == 0 ? W0 : seg == 1 ? W1 : seg == 2 ? W2 :
                       seg == 3 ? W3 : seg == 4 ? W4 : W5;
    const int K = Ks[seg], N = Ns[seg];
    __nv_bfloat16* dst = WT + Off[seg];

    int bx = blockIdx.x * 32;   // n block
    int by = blockIdx.y * 32;   // k block
    if (bx >= N || by >= K) return;

    int x = bx + threadIdx.x;
#pragma unroll
    for (int j = 0; j < 32; j += 8) {
        int y = by + threadIdx.y + j;
        if (x < N && y < K) t[threadIdx.y + j][threadIdx.x] = src[(size_t)y * N + x];
    }
    __syncthreads();
    x = by + threadIdx.x;
#pragma unroll
    for (int j = 0; j < 32; j += 8) {
        int y = bx + threadIdx.y + j;
        if (x < K && y < N)
            dst[(size_t)y * K + x] = __float2bfloat16_rn(t[threadIdx.x][threadIdx.y + j]);
    }
}

// Round value input to bf16 once
__global__ void round_kernel(const float* __restrict__ src,
                             __nv_bfloat16* __restrict__ dst, int n)
{
    int i = blockIdx.x * blockDim.x + threadIdx.x;
    if (i < n) dst[i] = __float2bfloat16_rn(src[i]);
}

// ---------------------------------------------------------------------------
// bf16 HMMA GEMM: C[M,N] = A[M,K] @ W[K,N] (+bias +add1 +add2, opt gelu)
// WT: pre-transposed [N][K] bf16. CTA 128x128, BK=32, 8 warps of 64x32.
// SMEM rows padded to 40 bf16 (80B) -> conflict-free LDSM + cp.async.
// Output: Cf (fp32) or Cb (bf16), whichever is non-null.
// ---------------------------------------------------------------------------
#define AST 10240                       // bytes per A stage (128 rows * 80B)
#define SM_BYTES (4 * AST)              // A0,A1,B0,B1

__global__ __launch_bounds__(256) void gemm_bf16(
    const __nv_bfloat16* __restrict__ A, const __nv_bfloat16* __restrict__ WT,
    const float* __restrict__ bias, const float* __restrict__ add1,
    const float* __restrict__ add2, float* __restrict__ Cf,
    __nv_bfloat16* __restrict__ Cb, int M, int N, int K, int gelu_flag)
{
    extern __shared__ char smem[];
    const uint32_t sbase = smem_u32(smem);
    const int tid  = threadIdx.x;
    const int wid  = tid >> 5;
    const int lane = tid & 31;
    const int wm   = wid >> 2;          // 0..1 (64 rows)
    const int wn   = wid & 3;           // 0..3 (32 cols)
    const int m0   = blockIdx.y * 128;
    const int n0   = blockIdx.x * 128;

    float acc[4][4][4];
#pragma unroll
    for (int i = 0; i < 4; i++)
#pragma unroll
        for (int j = 0; j < 4; j++)
#pragma unroll
            for (int r = 0; r < 4; r++) acc[i][j][r] = 0.f;

    const int nk = K >> 5;

    auto load_tile = [&](int s, int kt) {
        const int k0 = kt * 32;
#pragma unroll
        for (int t = 0; t < 2; t++) {
            int idx = tid + t * 256;
            int row = idx >> 2, c = idx & 3;
            int gm = m0 + row;
            int sz = (gm < M) ? 16 : 0;
            const __nv_bfloat16* src = A + (size_t)(sz ? gm : 0) * K + k0 + c * 8;
            uint32_t dst = sbase + (uint32_t)(s * AST + row * 80 + c * 16);
            CP_ASYNC16(dst, src, sz);
        }
#pragma unroll
        for (int t = 0; t < 2; t++) {
            int idx = tid + t * 256;
            int row = idx >> 2, c = idx & 3;
            int gn = n0 + row;
            int sz = (gn < N) ? 16 : 0;
            const __nv_bfloat16* src = WT + (size_t)(sz ? gn : 0) * K + k0 + c * 8;
            uint32_t dst = sbase + (uint32_t)(2 * AST + s * AST + row * 80 + c * 16);
            CP_ASYNC16(dst, src, sz);
        }
    };

    load_tile(0, 0);
    CP_COMMIT();

    const int quad = lane >> 3;         // 0..3
    const int qr   = lane & 7;

    for (int kt = 0; kt < nk; kt++) {
        const int s = kt & 1;
        if (kt + 1 < nk) {
            load_tile(s ^ 1, kt + 1);
            CP_COMMIT();
            CP_WAIT1();
        } else {
            CP_WAIT0();
        }
        __syncthreads();

        const uint32_t abase = sbase + s * AST;
        const uint32_t bbase = sbase + 2 * AST + s * AST;

#pragma unroll
        for (int ks = 0; ks < 2; ks++) {
            const int k0 = ks * 16;
            uint32_t a[4][4];
#pragma unroll
            for (int mi = 0; mi < 4; mi++) {
                int mrow = wm * 64 + mi * 16 + (quad & 1) * 8 + qr;
                uint32_t addr = abase + (uint32_t)(mrow * 80 + (k0 + (quad >> 1) * 8) * 2);
                LDSM_X4(a[mi][0], a[mi][1], a[mi][2], a[mi][3], addr);
            }
            uint32_t b[4][2];
#pragma unroll
            for (int nj = 0; nj < 2; nj++) {
                int nrow = wn * 32 + nj * 16 + ((quad >> 1) & 1) * 8 + qr;
                uint32_t addr = bbase + (uint32_t)(nrow * 80 + (k0 + (quad & 1) * 8) * 2);
                LDSM_X4(b[nj * 2][0], b[nj * 2][1], b[nj * 2 + 1][0], b[nj * 2 + 1][1], addr);
            }
#pragma unroll
            for (int mi = 0; mi < 4; mi++)
#pragma unroll
                for (int ni = 0; ni < 4; ni++)
                    mma_bf16(acc[mi][ni], a[mi], b[ni]);
        }
        __syncthreads();
    }

    // ---- epilogue ----
    const int g = lane >> 2;
    const int c2 = lane & 3;
#pragma unroll
    for (int mi = 0; mi < 4; mi++) {
#pragma unroll
        for (int ni = 0; ni < 4; ni++) {
            int row = m0 + wm * 64 + mi * 16 + g;
            int col = n0 + wn * 32 + ni * 8 + c2 * 2;
            if (col >= N) continue;
            float2 bs = *(const float2*)&bias[col];
#pragma unroll
            for (int half = 0; half < 2; half++) {
                int r = row + half * 8;
                if (r >= M) continue;
                size_t idx = (size_t)r * N + col;
                float vx = acc[mi][ni][half * 2 + 0] + bs.x;
                float vy = acc[mi][ni][half * 2 + 1] + bs.y;
                if (add1) {
                    float2 a1 = *(const float2*)&add1[idx];
                    vx += a1.x; vy += a1.y;
                }
                if (add2) {
                    float2 a2 = *(const float2*)&add2[idx];
                    vx += a2.x; vy += a2.y;
                }
                if (gelu_flag) {
                    vx = 0.5f * vx * (1.f + erff(vx * 0.70710678118654752f));
                    vy = 0.5f * vy * (1.f + erff(vy * 0.70710678118654752f));
                }
                if (Cf) {
                    float2 o; o.x = vx; o.y = vy;
                    *(float2*)&Cf[idx] = o;
                } else {
                    __nv_bfloat162 o;
                    o.x = __float2bfloat16_rn(vx);
                    o.y = __float2bfloat16_rn(vy);
                    *(__nv_bfloat162*)&Cb[idx] = o;
                }
            }
        }
    }
}

// ---------------------------------------------------------------------------
// LayerNorm: one warp per row of 256.
// out_f: fp32 normalized output (nullable)
// out_b: bf16 output (nullable). If pos != null, out_b = bf16(norm + pos),
//        else out_b = bf16(norm).
// ---------------------------------------------------------------------------
__global__ void ln_kernel(const float* __restrict__ x,
                          const float* __restrict__ gamma,
                          const float* __restrict__ beta,
                          const float* __restrict__ pos,
                          float* __restrict__ out_f,
                          __nv_bfloat16* __restrict__ out_b)
{
    int warp = (blockIdx.x * blockDim.x + threadIdx.x) >> 5;
    int lane = threadIdx.x & 31;
    if (warp >= BQ) return;

    const float* xr = x + (size_t)warp * EMBED;
    float v[8];
    float s = 0.f;
#pragma unroll
    for (int i = 0; i < 8; i++) { v[i] = xr[i * 32 + lane]; s += v[i]; }
#pragma unroll
    for (int o = 16; o > 0; o >>= 1) s += __shfl_xor_sync(0xFFFFFFFFu, s, o);
    float mean = s * (1.f / EMBED);

    float s2 = 0.f;
#pragma unroll
    for (int i = 0; i < 8; i++) { float d = v[i] - mean; s2 += d * d; }
#pragma unroll
    for (int o = 16; o > 0; o >>= 1) s2 += __shfl_xor_sync(0xFFFFFFFFu, s2, o);
    float rstd = rsqrtf(s2 * (1.f / EMBED) + 1e-5f);

    size_t base = (size_t)warp * EMBED;
#pragma unroll
    for (int i = 0; i < 8; i++) {
        int c = i * 32 + lane;
        float nv = (v[i] - mean) * rstd * gamma[c] + beta[c];
        if (out_f) out_f[base + c] = nv;
        if (out_b) {
            float ov = pos ? (nv + pos[base + c]) : nv;
            out_b[base + c] = __float2bfloat16_rn(ov);
        }
    }
}

// ---------------------------------------------------------------------------
// Deformable sampling with fused softmax: one warp per (b,q,h).
// Reads raw logits; each lane redundantly computes the 12-wide softmax.
// Output bf16 (feeds GEMM P as A operand).
// ---------------------------------------------------------------------------
__global__ void sample_kernel(const float* __restrict__ v,
                              const float* __restrict__ offs,
                              const float* __restrict__ logits,
                              const float* __restrict__ ref,
                              __nv_bfloat16* __restrict__ out)
{
    const int LH[3] = {60, 30, 15};
    const int LW[3] = {80, 40, 20};
    const int LS[3] = {0, 4800, 6000};

    int warp = (blockIdx.x * blockDim.x + threadIdx.x) >> 5;
    int lane = threadIdx.x & 31;
    if (warp >= BQ * HEADS) return;

    int h  = warp & 7;
    int bq = warp >> 3;
    int b  = bq / NQ;

    // fused softmax over 12 logits (broadcast loads, redundant per lane)
    const float* lg = logits + (size_t)bq * 96 + h * 12;
    float w[12];
    float mx = -1e30f;
#pragma unroll
    for (int i = 0; i < 12; i++) { w[i] = lg[i]; mx = fmaxf(mx, w[i]); }
    float ssum = 0.f;
#pragma unroll
    for (int i = 0; i < 12; i++) { w[i] = __expf(w[i] - mx); ssum += w[i]; }
    float inv = 1.f / ssum;

    float acc = 0.f;
    const float* offr = offs + (size_t)bq * 192 + h * 24;
    const float* refr = ref  + (size_t)bq * (LEVELS * 2);

#pragma unroll
    for (int l = 0; l < LEVELS; l++) {
        const int Hl = LH[l], Wl = LW[l];
        const float rx = refr[l * 2 + 0] * (float)Wl - 0.5f;
        const float ry = refr[l * 2 + 1] * (float)Hl - 0.5f;
        const float* vb = v + (((size_t)b * NV + LS[l]) * EMBED) + h * DH + lane;

#pragma unroll
        for (int p = 0; p < POINTS; p++) {
            float gx = rx + offr[l * 8 + p * 2 + 0];
            float gy = ry + offr[l * 8 + p * 2 + 1];
            float x0f = floorf(gx), y0f = floorf(gy);
            float wx = gx - x0f, wy = gy - y0f;
            int x0 = (int)x0f, y0 = (int)y0f;

            float w00 = (1.f - wx) * (1.f - wy);
            float w10 = wx * (1.f - wy);
            float w01 = (1.f - wx) * wy;
            float w11 = wx * wy;

            bool xv0 = (x0 >= 0) & (x0 < Wl);
            bool xv1 = (x0 + 1 >= 0) & (x0 + 1 < Wl);
            bool yv0 = (y0 >= 0) & (y0 < Hl);
            bool yv1 = (y0 + 1 >= 0) & (y0 + 1 < Hl);

            float sv = 0.f;
            if (xv0 & yv0) sv += w00 * vb[((size_t)(y0 * Wl + x0)) * EMBED];
            if (xv1 & yv0) sv += w10 * vb[((size_t)(y0 * Wl + x0 + 1)) * EMBED];
            if (xv0 & yv1) sv += w01 * vb[((size_t)((y0 + 1) * Wl + x0)) * EMBED];
            if (xv1 & yv1) sv += w11 * vb[((size_t)((y0 + 1) * Wl + x0 + 1)) * EMBED];

            acc = fmaf(w[l * 4 + p] * inv, sv, acc);
        }
    }

    out[(size_t)bq * EMBED + h * DH + lane] = __float2bfloat16_rn(acc);
}

// ---------------------------------------------------------------------------
// Launch
// ---------------------------------------------------------------------------
extern "C" void kernel_launch(void* const* d_in, const int* in_sizes, int n_in,
                              void* d_out, int out_size)
{
    (void)in_sizes; (void)n_in; (void)out_size;

    const float* query = (const float*)d_in[0];
    const float* value = (const float*)d_in[1];
    const float* qpos  = (const float*)d_in[2];
    const float* refp  = (const float*)d_in[3];
    const float* g1  = (const float*)d_in[6];
    const float* b1  = (const float*)d_in[7];
    const float* Wo  = (const float*)d_in[8];
    const float* bo  = (const float*)d_in[9];
    const float* Wa  = (const float*)d_in[10];
    const float* ba  = (const float*)d_in[11];
    const float* Wv  = (const float*)d_in[12];
    const float* bv  = (const float*)d_in[13];
    const float* Wp  = (const float*)d_in[14];
    const float* bp  = (const float*)d_in[15];
    const float* g2  = (const float*)d_in[16];
    const float* b2  = (const float*)d_in[17];
    const float* Wf1 = (const float*)d_in[18];
    const float* bf1 = (const float*)d_in[19];
    const float* Wf2 = (const float*)d_in[20];
    const float* bf2 = (const float*)d_in[21];
    float* out = (float*)d_out;

    float *qn, *offs, *aw, *v, *q;
    __nv_bfloat16 *qa, *vr, *samp, *q2, *hid, *wt;
    cudaGetSymbolAddress((void**)&qn,   g_qn);
    cudaGetSymbolAddress((void**)&qa,   g_qa);
    cudaGetSymbolAddress((void**)&offs, g_offs);
    cudaGetSymbolAddress((void**)&aw,   g_aw);
    cudaGetSymbolAddress((void**)&vr,   g_vr);
    cudaGetSymbolAddress((void**)&v,    g_v);
    cudaGetSymbolAddress((void**)&samp, g_samp);
    cudaGetSymbolAddress((void**)&q,    g_q);
    cudaGetSymbolAddress((void**)&q2,   g_q2);
    cudaGetSymbolAddress((void**)&hid,  g_hid);
    cudaGetSymbolAddress((void**)&wt,   g_WT);

    cudaFuncSetAttribute(gemm_bf16, cudaFuncAttributeMaxDynamicSharedMemorySize, SM_BYTES);

    // 0. transpose + bf16-round weights; round value
    transpose_all<<<dim3(32, 32, 6), dim3(32, 8)>>>(Wo, Wa, Wv, Wp, Wf1, Wf2, wt);
    round_kernel<<<(MV * EMBED + 255) / 256, 256>>>(value, vr, MV * EMBED);

    // 1. qn = LN1(query) fp32; qa = bf16(qn + query_pos)
    ln_kernel<<<2048, 256>>>(query, g1, b1, qpos, qn, qa);

    // 2. offsets and attention logits
    gemm_bf16<<<dim3(2, 128), 256, SM_BYTES>>>(qa, wt + WT_O, bo, nullptr, nullptr,
                                               offs, nullptr, BQ, 192, 256, 0);
    gemm_bf16<<<dim3(1, 128), 256, SM_BYTES>>>(qa, wt + WT_A, ba, nullptr, nullptr,
                                               aw, nullptr, BQ, 96, 256, 0);

    // 3. value projection
    gemm_bf16<<<dim3(2, 99), 256, SM_BYTES>>>(vr, wt + WT_V, bv, nullptr, nullptr,
                                              v, nullptr, MV, 256, 256, 0);

    // 4. deformable sampling (fused softmax), out bf16
    sample_kernel<<<(BQ * HEADS * 32) / 256, 256>>>(v, offs, aw, refp, samp);

    // 5. q = samp @ Wp + bp + qn + query
    gemm_bf16<<<dim3(2, 128), 256, SM_BYTES>>>(samp, wt + WT_P, bp, qn, query,
                                               q, nullptr, BQ, 256, 256, 0);

    // 6. q2 = bf16(LN2(q))
    ln_kernel<<<2048, 256>>>(q, g2, b2, nullptr, nullptr, q2);

    // 7. hid = bf16(gelu(q2 @ Wf1 + bf1))
    gemm_bf16<<<dim3(8, 128), 256, SM_BYTES>>>(q2, wt + WT_F1, bf1, nullptr, nullptr,
                                               nullptr, hid, BQ, 1024, 256, 1);

    // 8. out = q + hid @ Wf2 + bf2
    gemm_bf16<<<dim3(2, 128), 256, SM_BYTES>>>(hid, wt + WT_F2, bf2, q, nullptr,
                                               out, nullptr, BQ, 256, 1024, 0);
}

// round 6
// speedup vs baseline: 5.6283x; 1.0990x over previous
#include <cuda_runtime.h>
#include <cuda_bf16.h>
#include <math.h>
#include <stdint.h>

// ---------------------------------------------------------------------------
// Problem constants
// ---------------------------------------------------------------------------
#define BATCH   2
#define NQ      8192
#define EMBED   256
#define HEADS   8
#define DH      32
#define LEVELS  3
#define POINTS  4
#define NV      6300
#define BQ      (BATCH * NQ)   // 16384
#define MV      (BATCH * NV)   // 12600

// ---------------------------------------------------------------------------
// Scratch (device globals)
// ---------------------------------------------------------------------------
__device__ float          g_qn  [BQ * EMBED];   // LN1(query), fp32
__device__ __nv_bfloat16  g_qa  [BQ * EMBED];   // bf16(qn + query_pos)
__device__ float          g_oa  [BQ * 288];     // [offsets(192) | logits(96)] per row
__device__ __nv_bfloat16  g_vr  [MV * EMBED];   // bf16(value)
__device__ __nv_bfloat16  g_v   [MV * EMBED];   // bf16(value @ Wv + bv)
__device__ __nv_bfloat16  g_samp[BQ * EMBED];   // bf16 sampled output
__device__ float          g_q   [BQ * EMBED];
__device__ __nv_bfloat16  g_q2  [BQ * EMBED];   // bf16(LN2(q))
__device__ __nv_bfloat16  g_hid [BQ * 1024];    // bf16(gelu(...))
__device__ __nv_bfloat16  g_WT  [729088];       // transposed weights [N][K], bf16
__device__ float          g_boa [288];          // concat(bo, ba)

#define WT_OA  0        // 288 x 256  (Wo^T rows 0..191, Wa^T rows 192..287)
#define WT_A   49152
#define WT_V   73728    // 256 x 256
#define WT_P   139264   // 256 x 256
#define WT_F1  204800   // 1024 x 256
#define WT_F2  466944   // 256 x 1024

// ---------------------------------------------------------------------------
// Helpers
// ---------------------------------------------------------------------------
__device__ __forceinline__ uint32_t smem_u32(const void* p) {
    uint32_t a;
    asm("{ .reg .u64 t; cvta.to.shared.u64 t, %1; cvt.u32.u64 %0, t; }"
        : "=r"(a) : "l"(p));
    return a;
}
#define CP_ASYNC16(dst, src, sz) \
    asm volatile("cp.async.cg.shared.global [%0], [%1], 16, %2;" \
                 :: "r"(dst), "l"(src), "r"(sz) : "memory")
#define CP_COMMIT() asm volatile("cp.async.commit_group;" ::: "memory")
#define CP_WAIT1()  asm volatile("cp.async.wait_group 1;" ::: "memory")
#define CP_WAIT0()  asm volatile("cp.async.wait_group 0;" ::: "memory")

#define LDSM_X4(r0, r1, r2, r3, addr) \
    asm volatile("ldmatrix.sync.aligned.m8n8.x4.shared.b16 {%0,%1,%2,%3}, [%4];" \
                 : "=r"(r0), "=r"(r1), "=r"(r2), "=r"(r3) : "r"(addr))

__device__ __forceinline__ void mma_bf16(float* c, const uint32_t* a, const uint32_t* b) {
    asm volatile(
        "mma.sync.aligned.m16n8k16.row.col.f32.bf16.bf16.f32 "
        "{%0,%1,%2,%3}, {%4,%5,%6,%7}, {%8,%9}, {%0,%1,%2,%3};"
        : "+f"(c[0]), "+f"(c[1]), "+f"(c[2]), "+f"(c[3])
        : "r"(a[0]), "r"(a[1]), "r"(a[2]), "r"(a[3]), "r"(b[0]), "r"(b[1]));
}

// ---------------------------------------------------------------------------
// Weight transpose + bf16 round: WT[n][k] = bf16(W[k][n])
// ---------------------------------------------------------------------------
__global__ void transpose_all(const float* __restrict__ W0, const float* __restrict__ W1,
                              const float* __restrict__ W2, const float* __restrict__ W3,
                              const float* __restrict__ W4, const float* __restrict__ W5,
                              __nv_bfloat16* __restrict__ WT)
{
    __shared__ float t[32][33];
    const int seg = blockIdx.z;
    const int Ks[6]  = {256, 256, 256, 256, 256, 1024};
    const int Ns[6]  = {192,  96, 256, 256, 1024, 256};
    const int Off[6] = {WT_OA, WT_A, WT_V, WT_P, WT_F1, WT_F2};
    const float* src = seg == 0 ? W0 : seg == 1 ? W1 : seg == 2 ? W2 :
                       seg == 3 ? W3 : seg == 4 ? W4 : W5;
    const int K = Ks[seg], N = Ns[seg];
    __nv_bfloat16* dst = WT + Off[seg];

    int bx = blockIdx.x * 32;
    int by = blockIdx.y * 32;
    if (bx >= N || by >= K) return;

    int x = bx + threadIdx.x;
#pragma unroll
    for (int j = 0; j < 32; j += 8) {
        int y = by + threadIdx.y + j;
        if (x < N && y < K) t[threadIdx.y + j][threadIdx.x] = src[(size_t)y * N + x];
    }
    __syncthreads();
    x = by + threadIdx.x;
#pragma unroll
    for (int j = 0; j < 32; j += 8) {
        int y = bx + threadIdx.y + j;
        if (x < K && y < N)
            dst[(size_t)y * K + x] = __float2bfloat16_rn(t[threadIdx.x][threadIdx.y + j]);
    }
}

// Round value input to bf16; also build concat bias for the fused Wo|Wa GEMM
__global__ void round_kernel(const float* __restrict__ src,
                             __nv_bfloat16* __restrict__ dst, int n,
                             const float* __restrict__ bo,
                             const float* __restrict__ ba,
                             float* __restrict__ boa)
{
    int i = blockIdx.x * blockDim.x + threadIdx.x;
    if (i < n) dst[i] = __float2bfloat16_rn(src[i]);
    if (i < 288) boa[i] = (i < 192) ? bo[i] : ba[i - 192];
}

// ---------------------------------------------------------------------------
// bf16 HMMA GEMM, 3-stage cp.async pipeline, single barrier per k-tile.
// C[M,N] = A[M,K] @ W[K,N] (+bias +add1 +add2, opt gelu)
// CTA 128x128, BK=32, 8 warps of 64x32. 80B-padded smem rows.
// ---------------------------------------------------------------------------
#define ABYTES   10240                  // 128 rows * 80B
#define STG      20480                  // A + B per stage
#define SM_BYTES (3 * STG)              // 61440

__global__ __launch_bounds__(256) void gemm_bf16(
    const __nv_bfloat16* __restrict__ A, const __nv_bfloat16* __restrict__ WT,
    const float* __restrict__ bias, const float* __restrict__ add1,
    const float* __restrict__ add2, float* __restrict__ Cf,
    __nv_bfloat16* __restrict__ Cb, int M, int N, int K, int gelu_flag)
{
    extern __shared__ char smem[];
    const uint32_t sbase = smem_u32(smem);
    const int tid  = threadIdx.x;
    const int wid  = tid >> 5;
    const int lane = tid & 31;
    const int wm   = wid >> 2;
    const int wn   = wid & 3;
    const int m0   = blockIdx.y * 128;
    const int n0   = blockIdx.x * 128;

    float acc[4][4][4];
#pragma unroll
    for (int i = 0; i < 4; i++)
#pragma unroll
        for (int j = 0; j < 4; j++)
#pragma unroll
            for (int r = 0; r < 4; r++) acc[i][j][r] = 0.f;

    const int nk = K >> 5;

    auto load_tile = [&](int s, int kt) {
        const int k0 = kt * 32;
        const uint32_t base = sbase + (uint32_t)(s * STG);
#pragma unroll
        for (int t = 0; t < 2; t++) {
            int idx = tid + t * 256;
            int row = idx >> 2, c = idx & 3;
            int gm = m0 + row;
            int sz = (gm < M) ? 16 : 0;
            const __nv_bfloat16* src = A + (size_t)(sz ? gm : 0) * K + k0 + c * 8;
            CP_ASYNC16(base + (uint32_t)(row * 80 + c * 16), src, sz);
        }
#pragma unroll
        for (int t = 0; t < 2; t++) {
            int idx = tid + t * 256;
            int row = idx >> 2, c = idx & 3;
            int gn = n0 + row;
            int sz = (gn < N) ? 16 : 0;
            const __nv_bfloat16* src = WT + (size_t)(sz ? gn : 0) * K + k0 + c * 8;
            CP_ASYNC16(base + (uint32_t)(ABYTES + row * 80 + c * 16), src, sz);
        }
    };

    load_tile(0, 0); CP_COMMIT();
    load_tile(1, 1); CP_COMMIT();

    const int quad = lane >> 3;
    const int qr   = lane & 7;

    int s = 0;
    for (int kt = 0; kt < nk; kt++) {
        if (kt + 1 < nk) { CP_WAIT1(); } else { CP_WAIT0(); }
        __syncthreads();

        if (kt + 2 < nk) {
            load_tile((s + 2 >= 3) ? s - 1 : s + 2, kt + 2);
            CP_COMMIT();
        }

        const uint32_t abase = sbase + (uint32_t)(s * STG);
        const uint32_t bbase = abase + ABYTES;

#pragma unroll
        for (int ks = 0; ks < 2; ks++) {
            const int k0 = ks * 16;
            uint32_t a[4][4];
#pragma unroll
            for (int mi = 0; mi < 4; mi++) {
                int mrow = wm * 64 + mi * 16 + (quad & 1) * 8 + qr;
                uint32_t addr = abase + (uint32_t)(mrow * 80 + (k0 + (quad >> 1) * 8) * 2);
                LDSM_X4(a[mi][0], a[mi][1], a[mi][2], a[mi][3], addr);
            }
            uint32_t b[4][2];
#pragma unroll
            for (int nj = 0; nj < 2; nj++) {
                int nrow = wn * 32 + nj * 16 + ((quad >> 1) & 1) * 8 + qr;
                uint32_t addr = bbase + (uint32_t)(nrow * 80 + (k0 + (quad & 1) * 8) * 2);
                LDSM_X4(b[nj * 2][0], b[nj * 2][1], b[nj * 2 + 1][0], b[nj * 2 + 1][1], addr);
            }
#pragma unroll
            for (int mi = 0; mi < 4; mi++)
#pragma unroll
                for (int ni = 0; ni < 4; ni++)
                    mma_bf16(acc[mi][ni], a[mi], b[ni]);
        }
        s = (s + 1 >= 3) ? 0 : s + 1;
    }

    // ---- epilogue ----
    const int g = lane >> 2;
    const int c2 = lane & 3;
#pragma unroll
    for (int mi = 0; mi < 4; mi++) {
#pragma unroll
        for (int ni = 0; ni < 4; ni++) {
            int row = m0 + wm * 64 + mi * 16 + g;
            int col = n0 + wn * 32 + ni * 8 + c2 * 2;
            if (col >= N) continue;
            float2 bs = *(const float2*)&bias[col];
#pragma unroll
            for (int half = 0; half < 2; half++) {
                int r = row + half * 8;
                if (r >= M) continue;
                size_t idx = (size_t)r * N + col;
                float vx = acc[mi][ni][half * 2 + 0] + bs.x;
                float vy = acc[mi][ni][half * 2 + 1] + bs.y;
                if (add1) {
                    float2 a1 = *(const float2*)&add1[idx];
                    vx += a1.x; vy += a1.y;
                }
                if (add2) {
                    float2 a2 = *(const float2*)&add2[idx];
                    vx += a2.x; vy += a2.y;
                }
                if (gelu_flag) {
                    vx = 0.5f * vx * (1.f + erff(vx * 0.70710678118654752f));
                    vy = 0.5f * vy * (1.f + erff(vy * 0.70710678118654752f));
                }
                if (Cf) {
                    float2 o; o.x = vx; o.y = vy;
                    *(float2*)&Cf[idx] = o;
                } else {
                    __nv_bfloat162 o;
                    o.x = __float2bfloat16_rn(vx);
                    o.y = __float2bfloat16_rn(vy);
                    *(__nv_bfloat162*)&Cb[idx] = o;
                }
            }
        }
    }
}

// ---------------------------------------------------------------------------
// LayerNorm: one warp per row of 256.
// ---------------------------------------------------------------------------
__global__ void ln_kernel(const float* __restrict__ x,
                          const float* __restrict__ gamma,
                          const float* __restrict__ beta,
                          const float* __restrict__ pos,
                          float* __restrict__ out_f,
                          __nv_bfloat16* __restrict__ out_b)
{
    int warp = (blockIdx.x * blockDim.x + threadIdx.x) >> 5;
    int lane = threadIdx.x & 31;
    if (warp >= BQ) return;

    const float* xr = x + (size_t)warp * EMBED;
    float v[8];
    float s = 0.f;
#pragma unroll
    for (int i = 0; i < 8; i++) { v[i] = xr[i * 32 + lane]; s += v[i]; }
#pragma unroll
    for (int o = 16; o > 0; o >>= 1) s += __shfl_xor_sync(0xFFFFFFFFu, s, o);
    float mean = s * (1.f / EMBED);

    float s2 = 0.f;
#pragma unroll
    for (int i = 0; i < 8; i++) { float d = v[i] - mean; s2 += d * d; }
#pragma unroll
    for (int o = 16; o > 0; o >>= 1) s2 += __shfl_xor_sync(0xFFFFFFFFu, s2, o);
    float rstd = rsqrtf(s2 * (1.f / EMBED) + 1e-5f);

    size_t base = (size_t)warp * EMBED;
#pragma unroll
    for (int i = 0; i < 8; i++) {
        int c = i * 32 + lane;
        float nv = (v[i] - mean) * rstd * gamma[c] + beta[c];
        if (out_f) out_f[base + c] = nv;
        if (out_b) {
            float ov = pos ? (nv + pos[base + c]) : nv;
            out_b[base + c] = __float2bfloat16_rn(ov);
        }
    }
}

// ---------------------------------------------------------------------------
// Deformable sampling, fused softmax, bf16 value, pair-of-points scheme.
// One warp per (b,q,h). Lane groups of 16: group gg handles point 2j+gg of
// pair j; each lane covers 2 channels via bf16x2. Cross-group shfl reduce.
// ---------------------------------------------------------------------------
__global__ void sample_kernel(const __nv_bfloat16* __restrict__ v,
                              const float* __restrict__ oa,
                              const float* __restrict__ ref,
                              __nv_bfloat16* __restrict__ out)
{
    const int LH[3] = {60, 30, 15};
    const int LW[3] = {80, 40, 20};
    const int LS[3] = {0, 4800, 6000};

    int warp = (blockIdx.x * blockDim.x + threadIdx.x) >> 5;
    int lane = threadIdx.x & 31;
    if (warp >= BQ * HEADS) return;

    int h  = warp & 7;
    int bq = warp >> 3;
    int b  = bq / NQ;

    const float* row = oa + (size_t)bq * 288;
    const float* offr = row + h * 24;
    const float* lg   = row + 192 + h * 12;
    const float* refr = ref + (size_t)bq * (LEVELS * 2);

    // softmax over 12 logits (broadcast loads, redundant per lane)
    float w[12];
    float mx = -1e30f;
#pragma unroll
    for (int i = 0; i < 12; i++) { w[i] = lg[i]; mx = fmaxf(mx, w[i]); }
    float ssum = 0.f;
#pragma unroll
    for (int i = 0; i < 12; i++) { w[i] = __expf(w[i] - mx); ssum += w[i]; }
    float inv = 1.f / ssum;

    const int gg = lane >> 4;       // point-within-pair
    const int li = lane & 15;       // channel pair index

    float ax = 0.f, ay = 0.f;

#pragma unroll
    for (int j = 0; j < 6; j++) {
        const int l = j >> 1;                 // level (uniform across warp)
        const int p = 2 * (j & 1) + gg;       // point within level (differs by group)
        const int Hl = LH[l], Wl = LW[l];

        float gx = refr[l * 2 + 0] * (float)Wl - 0.5f + offr[l * 8 + p * 2 + 0];
        float gy = refr[l * 2 + 1] * (float)Hl - 0.5f + offr[l * 8 + p * 2 + 1];
        float x0f = floorf(gx), y0f = floorf(gy);
        float wx = gx - x0f, wy = gy - y0f;
        int x0 = (int)x0f, y0 = (int)y0f;

        float w00 = (1.f - wx) * (1.f - wy);
        float w10 = wx * (1.f - wy);
        float w01 = (1.f - wx) * wy;
        float w11 = wx * wy;

        bool xv0 = (x0 >= 0) & (x0 < Wl);
        bool xv1 = (x0 + 1 >= 0) & (x0 + 1 < Wl);
        bool yv0 = (y0 >= 0) & (y0 < Hl);
        bool yv1 = (y0 + 1 >= 0) & (y0 + 1 < Hl);

        const __nv_bfloat16* vb = v + (((size_t)b * NV + LS[l]) * EMBED) + h * DH + 2 * li;

        float sx = 0.f, sy = 0.f;
        if (xv0 & yv0) {
            float2 c = __bfloat1622float2(*(const __nv_bfloat162*)(vb + (size_t)(y0 * Wl + x0) * EMBED));
            sx += w00 * c.x; sy += w00 * c.y;
        }
        if (xv1 & yv0) {
            float2 c = __bfloat1622float2(*(const __nv_bfloat162*)(vb + (size_t)(y0 * Wl + x0 + 1) * EMBED));
            sx += w10 * c.x; sy += w10 * c.y;
        }
        if (xv0 & yv1) {
            float2 c = __bfloat1622float2(*(const __nv_bfloat162*)(vb + (size_t)((y0 + 1) * Wl + x0) * EMBED));
            sx += w01 * c.x; sy += w01 * c.y;
        }
        if (xv1 & yv1) {
            float2 c = __bfloat1622float2(*(const __nv_bfloat162*)(vb + (size_t)((y0 + 1) * Wl + x0 + 1) * EMBED));
            sx += w11 * c.x; sy += w11 * c.y;
        }

        float wt = w[l * 4 + p] * inv;
        ax = fmaf(wt, sx, ax);
        ay = fmaf(wt, sy, ay);
    }

    // combine the two point-groups (channels identical across groups)
    ax += __shfl_xor_sync(0xFFFFFFFFu, ax, 16);
    ay += __shfl_xor_sync(0xFFFFFFFFu, ay, 16);

    if (gg == 0) {
        __nv_bfloat162 o;
        o.x = __float2bfloat16_rn(ax);
        o.y = __float2bfloat16_rn(ay);
        *(__nv_bfloat162*)&out[(size_t)bq * EMBED + h * DH + 2 * li] = o;
    }
}

// ---------------------------------------------------------------------------
// Launch
// ---------------------------------------------------------------------------
extern "C" void kernel_launch(void* const* d_in, const int* in_sizes, int n_in,
                              void* d_out, int out_size)
{
    (void)in_sizes; (void)n_in; (void)out_size;

    const float* query = (const float*)d_in[0];
    const float* value = (const float*)d_in[1];
    const float* qpos  = (const float*)d_in[2];
    const float* refp  = (const float*)d_in[3];
    const float* g1  = (const float*)d_in[6];
    const float* b1  = (const float*)d_in[7];
    const float* Wo  = (const float*)d_in[8];
    const float* bo  = (const float*)d_in[9];
    const float* Wa  = (const float*)d_in[10];
    const float* ba  = (const float*)d_in[11];
    const float* Wv  = (const float*)d_in[12];
    const float* bv  = (const float*)d_in[13];
    const float* Wp  = (const float*)d_in[14];
    const float* bp  = (const float*)d_in[15];
    const float* g2  = (const float*)d_in[16];
    const float* b2  = (const float*)d_in[17];
    const float* Wf1 = (const float*)d_in[18];
    const float* bf1 = (const float*)d_in[19];
    const float* Wf2 = (const float*)d_in[20];
    const float* bf2 = (const float*)d_in[21];
    float* out = (float*)d_out;

    float *qn, *oa, *q, *boa;
    __nv_bfloat16 *qa, *vr, *v, *samp, *q2, *hid, *wt;
    cudaGetSymbolAddress((void**)&qn,   g_qn);
    cudaGetSymbolAddress((void**)&qa,   g_qa);
    cudaGetSymbolAddress((void**)&oa,   g_oa);
    cudaGetSymbolAddress((void**)&vr,   g_vr);
    cudaGetSymbolAddress((void**)&v,    g_v);
    cudaGetSymbolAddress((void**)&samp, g_samp);
    cudaGetSymbolAddress((void**)&q,    g_q);
    cudaGetSymbolAddress((void**)&q2,   g_q2);
    cudaGetSymbolAddress((void**)&hid,  g_hid);
    cudaGetSymbolAddress((void**)&wt,   g_WT);
    cudaGetSymbolAddress((void**)&boa,  g_boa);

    cudaFuncSetAttribute(gemm_bf16, cudaFuncAttributeMaxDynamicSharedMemorySize, SM_BYTES);

    // 0. transpose + bf16-round weights; round value; concat bias
    transpose_all<<<dim3(32, 32, 6), dim3(32, 8)>>>(Wo, Wa, Wv, Wp, Wf1, Wf2, wt);
    round_kernel<<<(MV * EMBED + 255) / 256, 256>>>(value, vr, MV * EMBED, bo, ba, boa);

    // 1. qn = LN1(query) fp32; qa = bf16(qn + query_pos)
    ln_kernel<<<2048, 256>>>(query, g1, b1, qpos, qn, qa);

    // 2. fused offsets + logits GEMM (N=288)
    gemm_bf16<<<dim3(3, 128), 256, SM_BYTES>>>(qa, wt + WT_OA, boa, nullptr, nullptr,
                                               oa, nullptr, BQ, 288, 256, 0);

    // 3. value projection -> bf16
    gemm_bf16<<<dim3(2, 99), 256, SM_BYTES>>>(vr, wt + WT_V, bv, nullptr, nullptr,
                                              nullptr, v, MV, 256, 256, 0);

    // 4. deformable sampling (fused softmax), bf16 in/out
    sample_kernel<<<(BQ * HEADS * 32) / 256, 256>>>(v, oa, refp, samp);

    // 5. q = samp @ Wp + bp + qn + query
    gemm_bf16<<<dim3(2, 128), 256, SM_BYTES>>>(samp, wt + WT_P, bp, qn, query,
                                               q, nullptr, BQ, 256, 256, 0);

    // 6. q2 = bf16(LN2(q))
    ln_kernel<<<2048, 256>>>(q, g2, b2, nullptr, nullptr, q2);

    // 7. hid = bf16(gelu(q2 @ Wf1 + bf1))
    gemm_bf16<<<dim3(8, 128), 256, SM_BYTES>>>(q2, wt + WT_F1, bf1, nullptr, nullptr,
                                               nullptr, hid, BQ, 1024, 256, 1);

    // 8. out = q + hid @ Wf2 + bf2
    gemm_bf16<<<dim3(2, 128), 256, SM_BYTES>>>(hid, wt + WT_F2, bf2, q, nullptr,
                                               out, nullptr, BQ, 256, 1024, 0);
}